// round 13
// baseline (speedup 1.0000x reference)
#include <cuda_runtime.h>
#include <cstdint>

typedef unsigned long long ull_t;

// ---- packed f32x2 helpers ----
__device__ __forceinline__ void ffma2(ull_t &acc, ull_t a, ull_t b) {
    asm volatile("fma.rn.f32x2 %0, %1, %2, %0;" : "+l"(acc) : "l"(a), "l"(b));
}
__device__ __forceinline__ ull_t ffma2o(ull_t a, ull_t b, ull_t c) {
    ull_t r; asm("fma.rn.f32x2 %0, %1, %2, %3;" : "=l"(r) : "l"(a), "l"(b), "l"(c));
    return r;
}
__device__ __forceinline__ ull_t add2(ull_t a, ull_t b) {
    ull_t r; asm("add.rn.f32x2 %0, %1, %2;" : "=l"(r) : "l"(a), "l"(b)); return r;
}
__device__ __forceinline__ float hsum2(ull_t v) {
    float lo, hi; asm("mov.b64 {%0,%1}, %2;" : "=f"(lo), "=f"(hi) : "l"(v));
    return lo + hi;
}
__device__ __forceinline__ void unpack2(float &lo, float &hi, ull_t v) {
    asm("mov.b64 {%0,%1}, %2;" : "=f"(lo), "=f"(hi) : "l"(v));
}
__device__ __forceinline__ ull_t pack2(float lo, float hi) {
    ull_t r; asm("mov.b64 %0, {%1, %2};" : "=l"(r) : "f"(lo), "f"(hi)); return r;
}
__device__ __forceinline__ ull_t mul2(ull_t a, ull_t b) {
    ull_t r; asm("mul.rn.f32x2 %0, %1, %2;" : "=l"(r) : "l"(a), "l"(b)); return r;
}

__device__ __forceinline__ void cp_async16(uint32_t dst, const void* src, int src_sz) {
    asm volatile("cp.async.cg.shared.global [%0], [%1], 16, %2;"
                 :: "r"(dst), "l"(src), "r"(src_sz));
}
__device__ __forceinline__ void cp_commit() {
    asm volatile("cp.async.commit_group;");
}
__device__ __forceinline__ void cp_wait1() {
    asm volatile("cp.async.wait_group 1;" ::: "memory");
}
__device__ __forceinline__ void named_bar(int id, int cnt) {
    asm volatile("bar.sync %0, %1;" :: "r"(id), "r"(cnt) : "memory");
}

// Dynamic smem layout (81920 B total):
//   hist : ull  [2][64][32]   h history ring (2 chunks deep), (h2q,h2q+1) pairs
//   xpb  : ull  [2][2][32][32] xp ring [ringbuf][batch][row][pair]
//   xb   : f32  [2][2][32*32]  raw x ring
#define SMEM_HIST 0
#define SMEM_XP   32768
#define SMEM_XB   65536
#define SMEM_TOTAL 81920

// =====================================================================
// Warp-synchronous warp-specialized kernel (R12 structure + tail surgery).
//   w0: recurrence batch0 (SMSP0)   w1: recurrence batch1 (SMSP1)
//   w2: producer  batch0 (SMSP2)   w3: producer  batch1 (SMSP3)
// Rec step: 16 broadcast LDS.128 of h, 64 FFMA2 (mul2-init), add2 tree,
// hsum + lp-fadd, relu, STS.64, then NEXT step's lp = ffma2o(hP,oma2,xpN)
// computed in the syncwarp shadow. No cross-warp sync in the step loop.
// Producers stage x (cp.async), compute xp one chunk ahead, flush the h
// history ring to gmem one chunk behind. Rendezvous: named bar (1+sb, 64).
// =====================================================================
__global__ void __launch_bounds__(128, 1)
ctrnn_ws5_kernel(const float* __restrict__ x,
                 const float* __restrict__ W_in,
                 const float* __restrict__ b_in,
                 const float* __restrict__ W_hh,
                 const float* __restrict__ b_hh,
                 float* __restrict__ out,
                 int B, int T)
{
    constexpr int H  = 64;
    constexpr int D  = 32;
    constexpr int CH = 32;

    extern __shared__ char smem[];
    ull_t* hist = (ull_t*)(smem + SMEM_HIST);   // [sb*2048 + slot*32 + q]
    ull_t* xpb  = (ull_t*)(smem + SMEM_XP);     // [rb*2048 + sb*1024 + r*32 + q]
    float* xb   = (float*)(smem + SMEM_XB);     // [rb*2048 + sb*1024 + r*D + d]

    const int tid  = threadIdx.x;
    const int wid  = tid >> 5;
    const int q    = tid & 31;        // channel-pair index
    const int sb   = wid & 1;         // batch slot
    const int role = wid >> 1;        // 0 = recurrence, 1 = producer
    const int b    = blockIdx.x * 2 + sb;
    const bool active = (b < B);
    const int bc   = active ? b : (B - 1);

    const float alpha = (float)(16.67 / 40.0);
    const float oma   = (float)(1.0 - 16.67 / 40.0);
    const ull_t alpha2 = pack2(alpha, alpha);
    const ull_t oma2   = pack2(oma, oma);

    const int nchunk = (T + CH - 1) / CH;

    if (role == 1) {
        // ===================== PRODUCER / FLUSHER (own SMSP) =====================
        ull_t iA[16], iB[16];
        {
            const ulonglong2* ra = reinterpret_cast<const ulonglong2*>(W_in + (2 * q) * D);
            const ulonglong2* rb = reinterpret_cast<const ulonglong2*>(W_in + (2 * q + 1) * D);
#pragma unroll
            for (int m = 0; m < 8; m++) {
                ulonglong2 va = ra[m], vb = rb[m];
                iA[2 * m] = mul2(va.x, alpha2); iA[2 * m + 1] = mul2(va.y, alpha2);
                iB[2 * m] = mul2(vb.x, alpha2); iB[2 * m + 1] = mul2(vb.y, alpha2);
            }
        }
        const float abA = alpha * (b_in[2 * q]     + b_hh[2 * q]);
        const float abB = alpha * (b_in[2 * q + 1] + b_hh[2 * q + 1]);

        auto issue_chunk = [&](int c, int buf) {
            const float* src = x + ((size_t)bc * T + (size_t)c * CH) * D;
            uint32_t dstb = (uint32_t)__cvta_generic_to_shared(&xb[buf * 2048 + sb * 1024]);
#pragma unroll
            for (int i = 0; i < 8; i++) {
                int off16 = q + 32 * i;          // 256 x 16B units per chunk
                int row   = off16 >> 3;          // 8 units per timestep row
                bool ok   = active && (c * CH + row) < T;
                const void* s = ok ? (const void*)((const char*)src + (size_t)off16 * 16)
                                   : (const void*)x;
                cp_async16(dstb + off16 * 16, s, ok ? 16 : 0);
            }
            cp_commit();
        };

        auto produce = [&](int c) {
            const int rb   = c & 1;
            const int tend = min(CH, T - c * CH);
            const float* xrow0 = &xb[rb * 2048 + sb * 1024];
            ull_t* dst = &xpb[rb * 2048 + sb * 1024];
            for (int r = 0; r < tend; r++) {
                const ulonglong2* xr =
                    reinterpret_cast<const ulonglong2*>(xrow0 + r * D);
                ull_t aA0 = 0ull, aA1 = 0ull, aB0 = 0ull, aB1 = 0ull;
#pragma unroll
                for (int m = 0; m < 8; m++) {
                    ulonglong2 v = xr[m];
                    ffma2(aA0, iA[2 * m],     v.x);
                    ffma2(aA1, iA[2 * m + 1], v.y);
                    ffma2(aB0, iB[2 * m],     v.x);
                    ffma2(aB1, iB[2 * m + 1], v.y);
                }
                float pA = hsum2(add2(aA0, aA1)) + abA;
                float pB = hsum2(add2(aB0, aB1)) + abB;
                dst[r * 32 + q] = pack2(pA, pB);
            }
        };

        auto flushc = [&](int c) {
            if (!active) return;
            const int tend = min(CH, T - c * CH);
            for (int r = 0; r < tend; r++) {
                int t = c * CH + r;
                ull_t v = hist[sb * 2048 + (t & 63) * 32 + q];
                *(ull_t*)(out + ((size_t)bc * T + t) * H + 2 * q) = v;
            }
        };

        issue_chunk(0, 0);
        if (nchunk > 1) issue_chunk(1, 1); else cp_commit();
        cp_wait1();
        __syncwarp();
        produce(0);
        named_bar(1 + sb, 64);     // xp chunk 0 ready

        for (int c = 0; c < nchunk; c++) {
            if (c + 2 < nchunk) issue_chunk(c + 2, c & 1); else cp_commit();
            if (c + 1 < nchunk) {
                cp_wait1();
                __syncwarp();
                produce(c + 1);
            }
            if (c > 0) flushc(c - 1);
            named_bar(1 + sb, 64);
        }
        flushc(nchunk - 1);
    } else {
        // ===================== RECURRENCE (warp-synchronous) =====================
        ull_t wA[32], wB[32];
        {
            const ulonglong2* ra = reinterpret_cast<const ulonglong2*>(W_hh + (2 * q) * H);
            const ulonglong2* rb = reinterpret_cast<const ulonglong2*>(W_hh + (2 * q + 1) * H);
#pragma unroll
            for (int m = 0; m < 16; m++) {
                ulonglong2 va = ra[m], vb = rb[m];
                wA[2 * m] = mul2(va.x, alpha2); wA[2 * m + 1] = mul2(va.y, alpha2);
                wB[2 * m] = mul2(vb.x, alpha2); wB[2 * m + 1] = mul2(vb.y, alpha2);
            }
        }

        ull_t hP = 0ull;                         // packed (hA,hB), prev step
        float lpA, lpB;                          // leak+xp for current step
        hist[sb * 2048 + 63 * 32 + q] = 0ull;    // h_{-1} = 0 (slot 63)
        __syncwarp();
        named_bar(1 + sb, 64);                   // xp chunk 0 ready

        // lp for t=0: oma*0 + xp0  (just xp0)
        unpack2(lpA, lpB, xpb[0 * 2048 + sb * 1024 + 0 * 32 + q]);

        for (int c = 0; c < nchunk; c++) {
            const int xr   = c & 1;
            const int tend = min(CH, T - c * CH);
            const ull_t* xps = &xpb[xr * 2048 + sb * 1024];
            const int base = c * CH;

#define STEP(tt)                                                                    \
    {                                                                               \
        const int t = base + (tt);                                                  \
        const ulonglong2* hp = reinterpret_cast<const ulonglong2*>(                 \
            &hist[sb * 2048 + ((t + 63) & 63) * 32]);                               \
        ulonglong2 hv0 = hp[0];                                                     \
        ulonglong2 hv1 = hp[1];                                                     \
        ull_t aA0 = mul2(wA[0], hv0.x), aA2 = mul2(wA[1], hv0.y);                   \
        ull_t aB0 = mul2(wB[0], hv0.x), aB2 = mul2(wB[1], hv0.y);                   \
        ull_t aA1 = mul2(wA[2], hv1.x), aA3 = mul2(wA[3], hv1.y);                   \
        ull_t aB1 = mul2(wB[2], hv1.x), aB3 = mul2(wB[3], hv1.y);                   \
        _Pragma("unroll")                                                           \
        for (int m = 2; m < 16; m++) {                                              \
            ulonglong2 hv = hp[m];                                                  \
            ffma2((m & 1) ? aA1 : aA0, wA[2 * m],     hv.x);                        \
            ffma2((m & 1) ? aA3 : aA2, wA[2 * m + 1], hv.y);                        \
            ffma2((m & 1) ? aB1 : aB0, wB[2 * m],     hv.x);                        \
            ffma2((m & 1) ? aB3 : aB2, wB[2 * m + 1], hv.y);                        \
        }                                                                           \
        float pA = hsum2(add2(add2(aA0, aA1), add2(aA2, aA3))) + lpA;               \
        float pB = hsum2(add2(add2(aB0, aB1), add2(aB2, aB3))) + lpB;               \
        float hA = fmaxf(pA, 0.0f);                                                 \
        float hB = fmaxf(pB, 0.0f);                                                 \
        hP = pack2(hA, hB);                                                         \
        hist[sb * 2048 + (t & 63) * 32 + q] = hP;                                   \
        /* next step's leak+xp in the syncwarp shadow (in-slot prefetch) */         \
        ull_t xN = xps[(((tt) + 1) & 31) * 32 + q];                                 \
        unpack2(lpA, lpB, ffma2o(hP, oma2, xN));                                    \
        __syncwarp();                                                               \
    }

            if (tend == CH) {
#pragma unroll 4
                for (int tt = 0; tt < CH; tt++) STEP(tt)
            } else {
                for (int tt = 0; tt < tend; tt++) STEP(tt)
            }
#undef STEP

            named_bar(1 + sb, 64);   // chunk done; flusher may read; next xp ready

            // recompute lp for row 0 of next chunk from the FRESH ring slot
            if (c + 1 < nchunk) {
                ull_t x0 = xpb[((c + 1) & 1) * 2048 + sb * 1024 + q];
                unpack2(lpA, lpB, ffma2o(hP, oma2, x0));
            }
        }

        // h_last appended after outputs
        if (active) {
            float hA, hB;
            unpack2(hA, hB, hP);
            *(ull_t*)(out + (size_t)B * T * H + (size_t)b * H + 2 * q) = pack2(hA, hB);
        }
    }
}

extern "C" void kernel_launch(void* const* d_in, const int* in_sizes, int n_in,
                              void* d_out, int out_size)
{
    const float* x    = (const float*)d_in[0];
    // d_in[1] = seq_lengths: forward-dead (mask only gates gradients)
    const float* W_in = (const float*)d_in[2];
    const float* b_in = (const float*)d_in[3];
    const float* W_hh = (const float*)d_in[4];
    const float* b_hh = (const float*)d_in[5];
    float* out = (float*)d_out;

    const int B = in_sizes[1];
    const int H = in_sizes[5];
    const int D = in_sizes[2] / H;
    const long long T = (long long)in_sizes[0] / ((long long)B * D);

    cudaFuncSetAttribute(ctrnn_ws5_kernel,
                         cudaFuncAttributeMaxDynamicSharedMemorySize, SMEM_TOTAL);

    const int grid = (B + 1) / 2;
    ctrnn_ws5_kernel<<<grid, 128, SMEM_TOTAL>>>(x, W_in, b_in, W_hh, b_hh,
                                                out, B, (int)T);
}

// round 14
// speedup vs baseline: 1.7215x; 1.7215x over previous
#include <cuda_runtime.h>
#include <cstdint>

typedef unsigned long long ull_t;

// ---- packed f32x2 helpers ----
__device__ __forceinline__ void ffma2(ull_t &acc, ull_t a, ull_t b) {
    asm volatile("fma.rn.f32x2 %0, %1, %2, %0;" : "+l"(acc) : "l"(a), "l"(b));
}
__device__ __forceinline__ ull_t add2(ull_t a, ull_t b) {
    ull_t r; asm("add.rn.f32x2 %0, %1, %2;" : "=l"(r) : "l"(a), "l"(b)); return r;
}
__device__ __forceinline__ float hsum2(ull_t v) {
    float lo, hi; asm("mov.b64 {%0,%1}, %2;" : "=f"(lo), "=f"(hi) : "l"(v));
    return lo + hi;
}
__device__ __forceinline__ void unpack2(float &lo, float &hi, ull_t v) {
    asm("mov.b64 {%0,%1}, %2;" : "=f"(lo), "=f"(hi) : "l"(v));
}
__device__ __forceinline__ ull_t pack2(float lo, float hi) {
    ull_t r; asm("mov.b64 %0, {%1, %2};" : "=l"(r) : "f"(lo), "f"(hi)); return r;
}
__device__ __forceinline__ ull_t mul2(ull_t a, ull_t b) {
    ull_t r; asm("mul.rn.f32x2 %0, %1, %2;" : "=l"(r) : "l"(a), "l"(b)); return r;
}

__device__ __forceinline__ void cp_async16(uint32_t dst, const void* src, int src_sz) {
    asm volatile("cp.async.cg.shared.global [%0], [%1], 16, %2;"
                 :: "r"(dst), "l"(src), "r"(src_sz));
}
__device__ __forceinline__ void cp_commit() {
    asm volatile("cp.async.commit_group;");
}
__device__ __forceinline__ void cp_wait1() {
    asm volatile("cp.async.wait_group 1;" ::: "memory");
}
__device__ __forceinline__ void named_bar(int id, int cnt) {
    asm volatile("bar.sync %0, %1;" :: "r"(id), "r"(cnt) : "memory");
}

// Dynamic smem layout (81920 B total):
//   hist : ull  [2][64][32]   h history ring (2 chunks deep), (h2q,h2q+1) pairs
//   xpb  : ull  [2][2][32][32] xp ring [ringbuf][batch][row][pair]
//   xb   : f32  [2][2][32*32]  raw x ring
#define SMEM_HIST 0
#define SMEM_XP   32768
#define SMEM_XB   65536
#define SMEM_TOTAL 81920

// =====================================================================
// Warp-synchronous warp-specialized kernel (R12 + xp register prefetch).
//   w0: recurrence batch0 (SMSP0)   w1: recurrence batch1 (SMSP1)
//   w2: producer  batch0 (SMSP2)   w3: producer  batch1 (SMSP3)
// Rec step: prefetch next xp (LDS hides under FFMA block), 16 broadcast
// LDS.128 of h, 64 FFMA2 with leak+xp folded into accumulator init, add2
// tree + hsum, relu, STS.64, unpack prefetched xp, __syncwarp. No
// cross-warp sync in the step loop. Producers stage x (cp.async), compute
// xp one chunk ahead, flush h history to gmem one chunk behind.
// =====================================================================
__global__ void __launch_bounds__(128, 1)
ctrnn_ws6_kernel(const float* __restrict__ x,
                 const float* __restrict__ W_in,
                 const float* __restrict__ b_in,
                 const float* __restrict__ W_hh,
                 const float* __restrict__ b_hh,
                 float* __restrict__ out,
                 int B, int T)
{
    constexpr int H  = 64;
    constexpr int D  = 32;
    constexpr int CH = 32;

    extern __shared__ char smem[];
    ull_t* hist = (ull_t*)(smem + SMEM_HIST);   // [sb*2048 + slot*32 + q]
    ull_t* xpb  = (ull_t*)(smem + SMEM_XP);     // [rb*2048 + sb*1024 + r*32 + q]
    float* xb   = (float*)(smem + SMEM_XB);     // [rb*2048 + sb*1024 + r*D + d]

    const int tid  = threadIdx.x;
    const int wid  = tid >> 5;
    const int q    = tid & 31;        // channel-pair index
    const int sb   = wid & 1;         // batch slot
    const int role = wid >> 1;        // 0 = recurrence, 1 = producer
    const int b    = blockIdx.x * 2 + sb;
    const bool active = (b < B);
    const int bc   = active ? b : (B - 1);

    const float alpha = (float)(16.67 / 40.0);
    const float oma   = (float)(1.0 - 16.67 / 40.0);
    const ull_t alpha2 = pack2(alpha, alpha);

    const int nchunk = (T + CH - 1) / CH;

    if (role == 1) {
        // ===================== PRODUCER / FLUSHER (own SMSP) =====================
        ull_t iA[16], iB[16];
        {
            const ulonglong2* ra = reinterpret_cast<const ulonglong2*>(W_in + (2 * q) * D);
            const ulonglong2* rb = reinterpret_cast<const ulonglong2*>(W_in + (2 * q + 1) * D);
#pragma unroll
            for (int m = 0; m < 8; m++) {
                ulonglong2 va = ra[m], vb = rb[m];
                iA[2 * m] = mul2(va.x, alpha2); iA[2 * m + 1] = mul2(va.y, alpha2);
                iB[2 * m] = mul2(vb.x, alpha2); iB[2 * m + 1] = mul2(vb.y, alpha2);
            }
        }
        const float abA = alpha * (b_in[2 * q]     + b_hh[2 * q]);
        const float abB = alpha * (b_in[2 * q + 1] + b_hh[2 * q + 1]);

        auto issue_chunk = [&](int c, int buf) {
            const float* src = x + ((size_t)bc * T + (size_t)c * CH) * D;
            uint32_t dstb = (uint32_t)__cvta_generic_to_shared(&xb[buf * 2048 + sb * 1024]);
#pragma unroll
            for (int i = 0; i < 8; i++) {
                int off16 = q + 32 * i;          // 256 x 16B units per chunk
                int row   = off16 >> 3;          // 8 units per timestep row
                bool ok   = active && (c * CH + row) < T;
                const void* s = ok ? (const void*)((const char*)src + (size_t)off16 * 16)
                                   : (const void*)x;
                cp_async16(dstb + off16 * 16, s, ok ? 16 : 0);
            }
            cp_commit();
        };

        auto produce = [&](int c) {
            const int rb   = c & 1;
            const int tend = min(CH, T - c * CH);
            const float* xrow0 = &xb[rb * 2048 + sb * 1024];
            ull_t* dst = &xpb[rb * 2048 + sb * 1024];
            for (int r = 0; r < tend; r++) {
                const ulonglong2* xr =
                    reinterpret_cast<const ulonglong2*>(xrow0 + r * D);
                ull_t aA0 = 0ull, aA1 = 0ull, aB0 = 0ull, aB1 = 0ull;
#pragma unroll
                for (int m = 0; m < 8; m++) {
                    ulonglong2 v = xr[m];
                    ffma2(aA0, iA[2 * m],     v.x);
                    ffma2(aA1, iA[2 * m + 1], v.y);
                    ffma2(aB0, iB[2 * m],     v.x);
                    ffma2(aB1, iB[2 * m + 1], v.y);
                }
                float pA = hsum2(add2(aA0, aA1)) + abA;
                float pB = hsum2(add2(aB0, aB1)) + abB;
                dst[r * 32 + q] = pack2(pA, pB);
            }
        };

        auto flushc = [&](int c) {
            if (!active) return;
            const int tend = min(CH, T - c * CH);
            for (int r = 0; r < tend; r++) {
                int t = c * CH + r;
                ull_t v = hist[sb * 2048 + (t & 63) * 32 + q];
                *(ull_t*)(out + ((size_t)bc * T + t) * H + 2 * q) = v;
            }
        };

        issue_chunk(0, 0);
        if (nchunk > 1) issue_chunk(1, 1); else cp_commit();
        cp_wait1();            // chunk 0 landed
        __syncwarp();          // intra-warp visibility
        produce(0);
        named_bar(1 + sb, 64); // xp chunk 0 ready

        for (int c = 0; c < nchunk; c++) {
            if (c + 2 < nchunk) issue_chunk(c + 2, c & 1); else cp_commit();
            if (c + 1 < nchunk) {
                cp_wait1();        // chunk c+1 landed
                __syncwarp();
                produce(c + 1);    // xp into ring slot (c+1)&1
            }
            if (c > 0) flushc(c - 1);   // flush finished chunk
            named_bar(1 + sb, 64);      // rec finished chunk c
        }
        flushc(nchunk - 1);
    } else {
        // ===================== RECURRENCE (warp-synchronous) =====================
        ull_t wA[32], wB[32];
        {
            const ulonglong2* ra = reinterpret_cast<const ulonglong2*>(W_hh + (2 * q) * H);
            const ulonglong2* rb = reinterpret_cast<const ulonglong2*>(W_hh + (2 * q + 1) * H);
#pragma unroll
            for (int m = 0; m < 16; m++) {
                ulonglong2 va = ra[m], vb = rb[m];
                wA[2 * m] = mul2(va.x, alpha2); wA[2 * m + 1] = mul2(va.y, alpha2);
                wB[2 * m] = mul2(vb.x, alpha2); wB[2 * m + 1] = mul2(vb.y, alpha2);
            }
        }

        float hA = 0.0f, hB = 0.0f;
        float xpA, xpB;                          // current step's xp (registers)
        hist[sb * 2048 + 63 * 32 + q] = 0ull;    // h_{-1} = 0 (slot 63)
        __syncwarp();
        named_bar(1 + sb, 64);                   // wait xp chunk 0

        // xp for t=0 from fresh ring slot 0
        unpack2(xpA, xpB, xpb[0 * 2048 + sb * 1024 + q]);

        for (int c = 0; c < nchunk; c++) {
            const int xr   = c & 1;
            const int tend = min(CH, T - c * CH);
            const ull_t* xps = &xpb[xr * 2048 + sb * 1024];
            const int base = c * CH;

#define STEP(tt)                                                                    \
    {                                                                               \
        const int t = base + (tt);                                                  \
        /* prefetch next step's xp: LDS hides under the FFMA block. In-slot */     \
        /* wrap at tt=31 reads stale row 0 (discarded; reloaded after bar). */     \
        ull_t xN = xps[(((tt) + 1) & 31) * 32 + q];                                 \
        ull_t aA0 = pack2(fmaf(hA, oma, xpA), 0.0f);                                \
        ull_t aB0 = pack2(fmaf(hB, oma, xpB), 0.0f);                                \
        ull_t aA1 = 0ull, aA2 = 0ull, aA3 = 0ull;                                   \
        ull_t aB1 = 0ull, aB2 = 0ull, aB3 = 0ull;                                   \
        const ulonglong2* hp = reinterpret_cast<const ulonglong2*>(                 \
            &hist[sb * 2048 + ((t + 63) & 63) * 32]);                               \
        _Pragma("unroll")                                                           \
        for (int m = 0; m < 16; m++) {                                              \
            ulonglong2 hv = hp[m];                                                  \
            ffma2((m & 1) ? aA1 : aA0, wA[2 * m],     hv.x);                        \
            ffma2((m & 1) ? aA3 : aA2, wA[2 * m + 1], hv.y);                        \
            ffma2((m & 1) ? aB1 : aB0, wB[2 * m],     hv.x);                        \
            ffma2((m & 1) ? aB3 : aB2, wB[2 * m + 1], hv.y);                        \
        }                                                                           \
        float pA = hsum2(add2(add2(aA0, aA1), add2(aA2, aA3)));                     \
        float pB = hsum2(add2(add2(aB0, aB1), add2(aB2, aB3)));                     \
        hA = fmaxf(pA, 0.0f);                                                       \
        hB = fmaxf(pB, 0.0f);                                                       \
        hist[sb * 2048 + (t & 63) * 32 + q] = pack2(hA, hB);                        \
        unpack2(xpA, xpB, xN);                                                      \
        __syncwarp();                                                               \
    }

            if (tend == CH) {
#pragma unroll 2
                for (int tt = 0; tt < CH; tt++) STEP(tt)
            } else {
                for (int tt = 0; tt < tend; tt++) STEP(tt)
            }
#undef STEP

            named_bar(1 + sb, 64);   // chunk done: flusher reads; next xp ready

            // reload xp row 0 from the FRESH ring slot for the next chunk
            if (c + 1 < nchunk)
                unpack2(xpA, xpB, xpb[((c + 1) & 1) * 2048 + sb * 1024 + q]);
        }

        // h_last appended after outputs
        if (active)
            *(ull_t*)(out + (size_t)B * T * H + (size_t)b * H + 2 * q) = pack2(hA, hB);
    }
}

extern "C" void kernel_launch(void* const* d_in, const int* in_sizes, int n_in,
                              void* d_out, int out_size)
{
    const float* x    = (const float*)d_in[0];
    // d_in[1] = seq_lengths: forward-dead (mask only gates gradients)
    const float* W_in = (const float*)d_in[2];
    const float* b_in = (const float*)d_in[3];
    const float* W_hh = (const float*)d_in[4];
    const float* b_hh = (const float*)d_in[5];
    float* out = (float*)d_out;

    const int B = in_sizes[1];
    const int H = in_sizes[5];
    const int D = in_sizes[2] / H;
    const long long T = (long long)in_sizes[0] / ((long long)B * D);

    cudaFuncSetAttribute(ctrnn_ws6_kernel,
                         cudaFuncAttributeMaxDynamicSharedMemorySize, SMEM_TOTAL);

    const int grid = (B + 1) / 2;
    ctrnn_ws6_kernel<<<grid, 128, SMEM_TOTAL>>>(x, W_in, b_in, W_hh, b_hh,
                                                out, B, (int)T);
}